// round 11
// baseline (speedup 1.0000x reference)
#include <cuda_runtime.h>
#include <math.h>

#define Nn 100000
#define Ee 3200000
#define Fin 256
#define SCAN_BS 512
#define SCAN_NB ((Nn + SCAN_BS - 1) / SCAN_BS)   // 196

// ---------------- scratch (device globals; no allocations allowed) ----------
__device__ float  g_dinv[Nn];
__device__ int    g_deg[Nn];
__device__ int    g_rowptr[Nn + 1];
__device__ int    g_pos[Nn];
__device__ int    g_bsum[SCAN_NB];
__device__ int    g_boff[SCAN_NB];
__device__ int2   g_csr[Ee];               // (src, norm-as-int) sorted by dst
__device__ float4 g_h1[(size_t)Nn * 8];    // x @ init_w1 (both stacks), [n][32] as [n][8]x4
__device__ float4 g_r1[(size_t)Nn * 8];    // x @ root_w1
__device__ float4 g_h2[(size_t)Nn * 8];    // h @ init_w2
__device__ float4 g_r2[(size_t)Nn * 8];    // h @ root_w2

// ---------------- zero deg ---------------------------------------------------
__global__ void k_zero() {
    int i = blockIdx.x * blockDim.x + threadIdx.x;
    if (i < Nn) g_deg[i] = 0;
}

// ---------------- degree ----------------------------------------------------
__global__ void k_deg(const int* __restrict__ ei) {
    int e = blockIdx.x * blockDim.x + threadIdx.x;
    if (e < Ee) {
        unsigned d = (unsigned)ei[Ee + e];
        if (d < Nn) atomicAdd(&g_deg[d], 1);
    }
}

__global__ void k_dinv() {
    int i = blockIdx.x * blockDim.x + threadIdx.x;
    if (i < Nn) {
        int d = g_deg[i];
        g_dinv[i] = (d > 0) ? rsqrtf((float)d) : 0.0f;
    }
}

// ---------------- exclusive scan of deg -> rowptr (3 kernels) ---------------
__global__ __launch_bounds__(SCAN_BS) void k_scan1() {
    __shared__ int sh[SCAN_BS];
    int t = threadIdx.x;
    int i = blockIdx.x * SCAN_BS + t;
    int v = (i < Nn) ? g_deg[i] : 0;
    sh[t] = v;
    __syncthreads();
    #pragma unroll
    for (int off = 1; off < SCAN_BS; off <<= 1) {
        int add = (t >= off) ? sh[t - off] : 0;
        __syncthreads();
        sh[t] += add;
        __syncthreads();
    }
    if (i < Nn) g_rowptr[i] = sh[t] - v;          // local exclusive
    if (t == SCAN_BS - 1) g_bsum[blockIdx.x] = sh[t];
}

__global__ __launch_bounds__(256) void k_scan2() {
    __shared__ int sh[256];
    int t = threadIdx.x;
    int v = (t < SCAN_NB) ? g_bsum[t] : 0;
    sh[t] = v;
    __syncthreads();
    #pragma unroll
    for (int off = 1; off < 256; off <<= 1) {
        int add = (t >= off) ? sh[t - off] : 0;
        __syncthreads();
        sh[t] += add;
        __syncthreads();
    }
    if (t < SCAN_NB) g_boff[t] = sh[t] - v;       // exclusive block offsets
}

__global__ void k_scan3() {
    int i = blockIdx.x * blockDim.x + threadIdx.x;
    if (i < Nn) {
        int r = g_rowptr[i] + g_boff[i >> 9];
        g_rowptr[i] = r;
        g_pos[i] = r;
    }
    if (i == 0) g_rowptr[Nn] = Ee;
}

// ---------------- CSR fill ---------------------------------------------------
__global__ void k_fill(const int* __restrict__ ei) {
    int e = blockIdx.x * blockDim.x + threadIdx.x;
    if (e >= Ee) return;
    unsigned s = (unsigned)ei[e];
    unsigned d = (unsigned)ei[Ee + e];
    if (s >= Nn || d >= Nn) return;
    float nrm = g_dinv[s] * g_dinv[d];
    int p = atomicAdd(&g_pos[d], 1);
    g_csr[p] = make_int2((int)s, __float_as_int(nrm));
}

// ---------------- GEMM1: x[N,256] -> h1[N,32], r1[N,32] ---------------------
// 256 nodes x 64 outs per block, 256 threads, 8x8 per thread, K-chunk 32.
__global__ __launch_bounds__(256) void k_gemm1(const float* __restrict__ x,
                                               const float* __restrict__ iw,
                                               const float* __restrict__ rw) {
    __shared__ __align__(16) float xs[32][260];  // [k][node], 260*4 % 16 == 0
    __shared__ __align__(16) float ws[32][68];   // [k][out],  272 % 16 == 0

    int n0 = blockIdx.x * 256;
    int t = threadIdx.x;
    int out8  = (t & 7) * 8;    // 0..56 (whole group within init or root half)
    int node8 = (t >> 3) * 8;   // 0..248

    float acc[8][8] = {};

    for (int kk = 0; kk < Fin; kk += 32) {
        int nl = t >> 5;        // 0..7
        int kl = t & 31;        // 0..31
        #pragma unroll
        for (int r = 0; r < 32; r++) {
            int node = n0 + nl + r * 8;
            xs[kl][nl + r * 8] = (node < Nn) ? x[(size_t)node * Fin + kk + kl] : 0.0f;
        }
        #pragma unroll
        for (int r = 0; r < 8; r++) {
            int j = t + r * 256;
            int kw = j >> 6;    // 0..31
            int c  = j & 63;    // 0..63
            int cc = c & 31;
            const float* wsrc = (c < 32) ? iw : rw;
            // weight layout [K=2][256][16]: (k,f,o) -> k*4096 + f*16 + o
            ws[kw][c] = wsrc[(cc >> 4) * 4096 + (kk + kw) * 16 + (cc & 15)];
        }
        __syncthreads();

        #pragma unroll
        for (int k = 0; k < 32; k++) {
            float4 a0 = *(const float4*)&xs[k][node8];
            float4 a1 = *(const float4*)&xs[k][node8 + 4];
            float4 w0 = *(const float4*)&ws[k][out8];
            float4 w1 = *(const float4*)&ws[k][out8 + 4];
            float xa[8] = {a0.x, a0.y, a0.z, a0.w, a1.x, a1.y, a1.z, a1.w};
            float wa[8] = {w0.x, w0.y, w0.z, w0.w, w1.x, w1.y, w1.z, w1.w};
            #pragma unroll
            for (int i = 0; i < 8; i++)
                #pragma unroll
                for (int j = 0; j < 8; j++)
                    acc[i][j] += xa[i] * wa[j];
        }
        __syncthreads();
    }

    float* dstbase = (out8 < 32) ? (float*)g_h1 : (float*)g_r1;
    int coff = out8 & 31;
    #pragma unroll
    for (int i = 0; i < 8; i++) {
        int node = n0 + node8 + i;
        if (node >= Nn) continue;
        float* p = dstbase + (size_t)node * 32 + coff;
        *(float4*)p       = make_float4(acc[i][0], acc[i][1], acc[i][2], acc[i][3]);
        *(float4*)(p + 4) = make_float4(acc[i][4], acc[i][5], acc[i][6], acc[i][7]);
    }
}

// ---------------- gather aggregation core (warp per node) -------------------
// 4 edge-groups x 8 feature-lanes; returns per-lane feature value agg[lane].
__device__ __forceinline__ float gather_agg(int n, int lane, const float4* __restrict__ h) {
    int g = lane >> 3, sub = lane & 7;
    int beg = g_rowptr[n], end = g_rowptr[n + 1];
    float4 acc = make_float4(0.f, 0.f, 0.f, 0.f);
    for (int i = beg + g; i < end; i += 4) {
        int2 cs = __ldg(&g_csr[i]);
        float nrm = __int_as_float(cs.y);
        float4 v = __ldg(&h[(size_t)cs.x * 8 + sub]);
        acc.x += v.x * nrm; acc.y += v.y * nrm;
        acc.z += v.z * nrm; acc.w += v.w * nrm;
    }
    // reduce over the 4 groups (xor 8, 16) — all lanes end with full sums
    #pragma unroll
    for (int off = 8; off <= 16; off <<= 1) {
        acc.x += __shfl_xor_sync(0xffffffffu, acc.x, off);
        acc.y += __shfl_xor_sync(0xffffffffu, acc.y, off);
        acc.z += __shfl_xor_sync(0xffffffffu, acc.z, off);
        acc.w += __shfl_xor_sync(0xffffffffu, acc.w, off);
    }
    // transpose: lane l wants feature l = 4*(l>>2) + (l&3); source sub = l>>2
    int srcl = lane >> 2;
    float fx = __shfl_sync(0xffffffffu, acc.x, srcl);
    float fy = __shfl_sync(0xffffffffu, acc.y, srcl);
    float fz = __shfl_sync(0xffffffffu, acc.z, srcl);
    float fw = __shfl_sync(0xffffffffu, acc.w, srcl);
    int c = lane & 3;
    return (c == 0) ? fx : (c == 1) ? fy : (c == 2) ? fz : fw;
}

// ---------------- layer1: gather + combine + tiny GEMM2 ---------------------
__global__ __launch_bounds__(256) void k_gather1(const float* __restrict__ b1,
                                                 const float* __restrict__ iw2,
                                                 const float* __restrict__ rw2,
                                                 float* __restrict__ outAgg) {
    unsigned n = (blockIdx.x * 256u + threadIdx.x) >> 5;
    if (n >= Nn) return;
    int lane = threadIdx.x & 31;
    size_t idx = (size_t)n * 32 + lane;

    float aggv = gather_agg(n, lane, g_h1);

    float v = aggv + ((const float*)g_r1)[idx] + b1[lane];
    v = fmaxf(v, 0.0f);
    // lane = k*16 + o ; pair-mean across stacks -> all lanes hold h[o = lane&15]
    float h = 0.5f * (v + __shfl_xor_sync(0xffffffffu, v, 16));

    if (lane < 16) outAgg[(size_t)n * 16 + lane] = h;

    // weights [2][16][16]: out lane -> k=lane>>4, o=lane&15
    int base = (lane >> 4) * 256 + (lane & 15);
    float ai = 0.0f, ar = 0.0f;
    #pragma unroll
    for (int f = 0; f < 16; f++) {
        float hf = __shfl_sync(0xffffffffu, h, f);
        ai += hf * iw2[base + f * 16];
        ar += hf * rw2[base + f * 16];
    }
    ((float*)g_h2)[idx] = ai;
    ((float*)g_r2)[idx] = ar;
}

// ---------------- layer2: gather + logits + log_softmax ---------------------
__global__ __launch_bounds__(256) void k_gather2(const float* __restrict__ b2,
                                                 float* __restrict__ out) {
    unsigned n = (blockIdx.x * 256u + threadIdx.x) >> 5;
    if (n >= Nn) return;
    int lane = threadIdx.x & 31;
    size_t idx = (size_t)n * 32 + lane;

    float aggv = gather_agg(n, lane, g_h2);

    float v = aggv + ((const float*)g_r2)[idx] + b2[lane];
    v = 0.5f * (v + __shfl_xor_sync(0xffffffffu, v, 16));  // mean over stacks

    float m = v;
    #pragma unroll
    for (int o = 8; o; o >>= 1) m = fmaxf(m, __shfl_xor_sync(0xffffffffu, m, o));
    float e = expf(v - m);
    float s = e;
    #pragma unroll
    for (int o = 8; o; o >>= 1) s += __shfl_xor_sync(0xffffffffu, s, o);
    float r = v - m - logf(s);

    if (lane < 16) out[(size_t)n * 16 + lane] = r;
}

// ---------------- launch ------------------------------------------------------
extern "C" void kernel_launch(void* const* d_in, const int* in_sizes, int n_in,
                              void* d_out, int out_size) {
    const float* x   = (const float*)d_in[0];
    const int*   ei  = (const int*)d_in[1];      // int32 edge_index [2, E]
    const float* iw1 = (const float*)d_in[2];
    const float* rw1 = (const float*)d_in[3];
    const float* b1  = (const float*)d_in[4];
    const float* iw2 = (const float*)d_in[5];
    const float* rw2 = (const float*)d_in[6];
    const float* b2  = (const float*)d_in[7];
    float* out = (float*)d_out;

    k_zero<<<(Nn + 255) / 256, 256>>>();
    k_deg<<<(Ee + 255) / 256, 256>>>(ei);
    k_dinv<<<(Nn + 255) / 256, 256>>>();

    k_scan1<<<SCAN_NB, SCAN_BS>>>();
    k_scan2<<<1, 256>>>();
    k_scan3<<<(Nn + 255) / 256, 256>>>();

    k_gemm1<<<(Nn + 255) / 256, 256>>>(x, iw1, rw1);   // overlaps nothing but independent
    k_fill<<<(Ee + 255) / 256, 256>>>(ei);

    unsigned node_warp_blocks = (Nn * 32 + 255) / 256;
    k_gather1<<<node_warp_blocks, 256>>>(b1, iw2, rw2, out + (size_t)Nn * 16);
    k_gather2<<<node_warp_blocks, 256>>>(b2, out);
}